// round 9
// baseline (speedup 1.0000x reference)
#include <cuda_runtime.h>
#include <cuda_fp16.h>
#include <mma.h>
using namespace nvcuda;

#define NN 10000
#define NN_PAD 10048               // 157 * 64 (padding rows stay zero forever)
#define NE 640000
#define DD 128
#define CAP 160                    // Poisson(64) tail @160 ~ 1e-30
#define GEMM_TILES 157             // ceil(10000/64)
#define SCAT_BLOCKS 625            // 625 * 1024 = 640000 edges exactly
#define GRID_FUSED (GEMM_TILES * 5)   // 785: 1 gemm : 4 scatter
#define CVT_ELEMS (NN * DD + DD * DD) // 1296384

// ---- device scratch (static; zero-initialized at module load) ----
__device__ __half g_Ah[NN_PAD * DD];   // nodes in fp16
__device__ __half g_Wh[DD * DD];       // W in fp16
__device__ __half g_Yh[NN * DD];       // nodes @ W in fp16
__device__ int    g_counts[NN];        // scatter cursor == degree; reset by agg
__device__ int    g_sorted[NN * CAP];  // sender ids bucketed by receiver

// ---- K0: convert nodes+W to fp16; 32 elems (8 float4) per thread ----
__global__ void __launch_bounds__(256)
cvt_kernel(const float* __restrict__ nodes, const float* __restrict__ W) {
    int base = (blockIdx.x * 256 + threadIdx.x) * 32;
    const float4* s;
    __half* d;
    if (base < NN * DD) {
        s = reinterpret_cast<const float4*>(nodes + base);
        d = g_Ah + base;
    } else if (base < CVT_ELEMS) {
        int off = base - NN * DD;
        s = reinterpret_cast<const float4*>(W + off);
        d = g_Wh + off;
    } else return;
#pragma unroll
    for (int j = 0; j < 8; j++) {
        float4 v = s[j];
        __half2 h0 = __floats2half2_rn(v.x, v.y);
        __half2 h1 = __floats2half2_rn(v.z, v.w);
        uint2 u = make_uint2(*reinterpret_cast<unsigned*>(&h0),
                             *reinterpret_cast<unsigned*>(&h1));
        *reinterpret_cast<uint2*>(d + j * 4) = u;
    }
}

// ---- K1: fused wmma GEMM (bid%5==0) + edge scatter 4-wide (others) ----
__global__ void __launch_bounds__(256)
fused_kernel(const int* __restrict__ senders,
             const int* __restrict__ receivers) {
    __shared__ __half sW[DD * DD];       // 32 KB, W staged once per gemm block
    __shared__ float  stage[8][256];     // 8 KB, per-warp epilogue staging

    const int t = threadIdx.x;           // 256
    const int m = blockIdx.x % 5;

    if (m != 0) {
        // ---------- scatter role: 1024 edges per block, 4 per thread ----------
        int s = (blockIdx.x / 5) * 4 + (m - 1);   // 0..627
        if (s < SCAT_BLOCKS) {
            int e0 = s * 1024 + t * 4;
            int4 snd = *reinterpret_cast<const int4*>(&senders[e0]);
            int4 rcv = *reinterpret_cast<const int4*>(&receivers[e0]);
            int p0 = atomicAdd(&g_counts[rcv.x], 1);
            int p1 = atomicAdd(&g_counts[rcv.y], 1);
            int p2 = atomicAdd(&g_counts[rcv.z], 1);
            int p3 = atomicAdd(&g_counts[rcv.w], 1);
            g_sorted[rcv.x * CAP + p0] = snd.x;
            g_sorted[rcv.y * CAP + p1] = snd.y;
            g_sorted[rcv.z * CAP + p2] = snd.z;
            g_sorted[rcv.w * CAP + p3] = snd.w;
        }
        return;
    }

    // ---------- gemm role: rows [q*64, q*64+64), all 128 cols ----------
    const int q    = blockIdx.x / 5;     // 0..156
    const int warp = t >> 5;
    const int lane = t & 31;
    const int n0   = warp * 16;
    const int row0 = q * 64;

    // stage W into smem: 32768 B, 16 B per thread per iter, 8 iters
    {
        const uint4* src = reinterpret_cast<const uint4*>(g_Wh);
        uint4* dst = reinterpret_cast<uint4*>(sW);
#pragma unroll
        for (int j = 0; j < 8; j++) dst[t + j * 256] = src[t + j * 256];
    }
    __syncthreads();

    wmma::fragment<wmma::accumulator, 16, 16, 16, float> c[4];
#pragma unroll
    for (int r = 0; r < 4; r++) wmma::fill_fragment(c[r], 0.0f);

#pragma unroll
    for (int k0 = 0; k0 < 8; k0++) {     // K = 8 * 16
        wmma::fragment<wmma::matrix_b, 16, 16, 16, __half, wmma::row_major> bf;
        wmma::load_matrix_sync(bf, sW + (k0 * 16) * DD + n0, DD);
#pragma unroll
        for (int r = 0; r < 4; r++) {
            wmma::fragment<wmma::matrix_a, 16, 16, 16, __half, wmma::row_major> af;
            wmma::load_matrix_sync(af, g_Ah + (row0 + r * 16) * DD + k0 * 16, DD);
            wmma::mma_sync(c[r], af, bf, c[r]);
        }
    }

    // epilogue: fp32 stage -> fp16 g_Yh, 8 elems (16 B) per lane per tile
#pragma unroll
    for (int r = 0; r < 4; r++) {
        wmma::store_matrix_sync(&stage[warp][0], c[r], 16, wmma::mem_row_major);
        __syncwarp();
        const float* src = &stage[warp][lane * 8];
        int grow = row0 + r * 16 + (lane >> 1);
        if (grow < NN) {
            __half2 h[4];
#pragma unroll
            for (int j = 0; j < 4; j++)
                h[j] = __floats2half2_rn(src[2 * j], src[2 * j + 1]);
            *reinterpret_cast<uint4*>(&g_Yh[grow * DD + n0 + (lane & 1) * 8]) =
                *reinterpret_cast<uint4*>(&h[0]);
        }
        __syncwarp();
    }
}

// ---- helper: reinterpret uint as half2 ----
__device__ __forceinline__ __half2 h2(unsigned int u) {
    return *reinterpret_cast<__half2*>(&u);
}

// ---- K2: warp-per-node aggregation (R7 verbatim: 8-deep LDG.64 + fp16 tree) ----
__global__ void __launch_bounds__(256)
agg_kernel(const float* __restrict__ b, float* __restrict__ out) {
    int warp = (blockIdx.x * blockDim.x + threadIdx.x) >> 5;
    int lane = threadIdx.x & 31;
    if (warp >= NN) return;

    const int deg  = g_counts[warp];
    const int base = warp * CAP;

    const uint2* Y2 = reinterpret_cast<const uint2*>(g_Yh);
    float4 acc = make_float4(0.f, 0.f, 0.f, 0.f);

    int i = 0;
    for (; i + 7 < deg; i += 8) {
        int4 ia = *reinterpret_cast<const int4*>(&g_sorted[base + i]);
        int4 ib = *reinterpret_cast<const int4*>(&g_sorted[base + i + 4]);
        uint2 v0 = Y2[ia.x * 32 + lane];
        uint2 v1 = Y2[ia.y * 32 + lane];
        uint2 v2 = Y2[ia.z * 32 + lane];
        uint2 v3 = Y2[ia.w * 32 + lane];
        uint2 v4 = Y2[ib.x * 32 + lane];
        uint2 v5 = Y2[ib.y * 32 + lane];
        uint2 v6 = Y2[ib.z * 32 + lane];
        uint2 v7 = Y2[ib.w * 32 + lane];
        __half2 pa0 = __hadd2(h2(v0.x), h2(v1.x)), pa1 = __hadd2(h2(v2.x), h2(v3.x));
        __half2 pa2 = __hadd2(h2(v4.x), h2(v5.x)), pa3 = __hadd2(h2(v6.x), h2(v7.x));
        __half2 pb0 = __hadd2(h2(v0.y), h2(v1.y)), pb1 = __hadd2(h2(v2.y), h2(v3.y));
        __half2 pb2 = __hadd2(h2(v4.y), h2(v5.y)), pb3 = __hadd2(h2(v6.y), h2(v7.y));
        __half2 qa = __hadd2(__hadd2(pa0, pa1), __hadd2(pa2, pa3));
        __half2 qb = __hadd2(__hadd2(pb0, pb1), __hadd2(pb2, pb3));
        float2 fa = __half22float2(qa);
        float2 fb = __half22float2(qb);
        acc.x += fa.x; acc.y += fa.y; acc.z += fb.x; acc.w += fb.y;
    }
    for (; i + 3 < deg; i += 4) {
        int4 ia = *reinterpret_cast<const int4*>(&g_sorted[base + i]);
        uint2 v0 = Y2[ia.x * 32 + lane];
        uint2 v1 = Y2[ia.y * 32 + lane];
        uint2 v2 = Y2[ia.z * 32 + lane];
        uint2 v3 = Y2[ia.w * 32 + lane];
        __half2 qa = __hadd2(__hadd2(h2(v0.x), h2(v1.x)), __hadd2(h2(v2.x), h2(v3.x)));
        __half2 qb = __hadd2(__hadd2(h2(v0.y), h2(v1.y)), __hadd2(h2(v2.y), h2(v3.y)));
        float2 fa = __half22float2(qa);
        float2 fb = __half22float2(qb);
        acc.x += fa.x; acc.y += fa.y; acc.z += fb.x; acc.w += fb.y;
    }
    for (; i < deg; i++) {
        int s0 = g_sorted[base + i];
        uint2 v = Y2[s0 * 32 + lane];
        float2 fa = __half22float2(h2(v.x));
        float2 fb = __half22float2(h2(v.y));
        acc.x += fa.x; acc.y += fa.y; acc.z += fb.x; acc.w += fb.y;
    }

    if (lane == 0) g_counts[warp] = 0;   // reset cursor for next replay

    float sc = 1.0f / (float)max(deg, 1);
    float4 bv = reinterpret_cast<const float4*>(b)[lane];
    float4 o;
    o.x = acc.x * sc + bv.x;
    o.y = acc.y * sc + bv.y;
    o.z = acc.z * sc + bv.z;
    o.w = acc.w * sc + bv.w;
    reinterpret_cast<float4*>(out)[warp * 32 + lane] = o;
}

extern "C" void kernel_launch(void* const* d_in, const int* in_sizes, int n_in,
                              void* d_out, int out_size) {
    const float* nodes     = (const float*)d_in[0];
    const int*   senders   = (const int*)d_in[1];
    const int*   receivers = (const int*)d_in[2];
    const float* W         = (const float*)d_in[3];
    const float* b         = (const float*)d_in[4];
    float*       out       = (float*)d_out;

    cvt_kernel<<<(CVT_ELEMS / 32 + 255) / 256, 256>>>(nodes, W);   // 159 blocks
    fused_kernel<<<GRID_FUSED, 256>>>(senders, receivers);
    agg_kernel<<<(NN * 32 + 255) / 256, 256>>>(b, out);
}

// round 10
// speedup vs baseline: 1.4675x; 1.4675x over previous
#include <cuda_runtime.h>
#include <cuda_fp16.h>
#include <mma.h>
using namespace nvcuda;

#define NN 10000
#define NE 640000
#define DD 128
#define CAP 160                    // Poisson(64) tail @160 ~ 1e-30
#define GEMM_TILES 157             // ceil(10000/64)
#define SCAT_BLOCKS 625            // 625 * 1024 = 640000 edges exactly

// ---- device scratch (static; zero-initialized at module load) ----
__device__ __half g_Yh[NN * DD];       // nodes @ W in fp16
__device__ int    g_counts[NN];        // scatter cursor == degree; reset by agg
__device__ int    g_sorted[NN * CAP];  // sender ids bucketed by receiver

// ---- K1: tensor-core GEMM, fp32->fp16 conversion fused in-kernel ----
// 64 rows x 128 cols per block; A tile + full W staged as fp16 in smem (48KB).
__global__ void __launch_bounds__(256)
gemm_kernel(const float* __restrict__ nodes, const float* __restrict__ W) {
    __shared__ __half sA[64 * DD];       // 16 KB (reused as fp32 epilogue stage)
    __shared__ __half sW[DD * DD];       // 32 KB

    const int t    = threadIdx.x;        // 256
    const int row0 = blockIdx.x * 64;

    // load+convert A tile: 64x128 fp32 = 2048 float4, 8 per thread
    const float4* A4 = reinterpret_cast<const float4*>(nodes);
#pragma unroll
    for (int j = 0; j < 8; j++) {
        int i  = t + j * 256;
        int r  = i >> 5, c4 = i & 31;
        int gr = row0 + r;
        float4 v = make_float4(0.f, 0.f, 0.f, 0.f);
        if (gr < NN) v = A4[gr * 32 + c4];
        __half2 h0 = __floats2half2_rn(v.x, v.y);
        __half2 h1 = __floats2half2_rn(v.z, v.w);
        *reinterpret_cast<uint2*>(&sA[r * DD + c4 * 4]) =
            make_uint2(*reinterpret_cast<unsigned*>(&h0),
                       *reinterpret_cast<unsigned*>(&h1));
    }
    // load+convert W: 128x128 fp32 = 4096 float4, 16 per thread (L2-hot)
    const float4* W4 = reinterpret_cast<const float4*>(W);
#pragma unroll
    for (int j = 0; j < 16; j++) {
        int i = t + j * 256;
        int r = i >> 5, c4 = i & 31;
        float4 v = W4[i];
        __half2 h0 = __floats2half2_rn(v.x, v.y);
        __half2 h1 = __floats2half2_rn(v.z, v.w);
        *reinterpret_cast<uint2*>(&sW[r * DD + c4 * 4]) =
            make_uint2(*reinterpret_cast<unsigned*>(&h0),
                       *reinterpret_cast<unsigned*>(&h1));
    }
    __syncthreads();

    const int warp = t >> 5;
    const int lane = t & 31;
    const int n0   = warp * 16;          // 8 warps cover 128 output cols

    wmma::fragment<wmma::accumulator, 16, 16, 16, float> c[4];
#pragma unroll
    for (int r = 0; r < 4; r++) wmma::fill_fragment(c[r], 0.0f);

#pragma unroll
    for (int k0 = 0; k0 < 8; k0++) {     // K = 8 * 16
        wmma::fragment<wmma::matrix_b, 16, 16, 16, __half, wmma::row_major> bf;
        wmma::load_matrix_sync(bf, sW + (k0 * 16) * DD + n0, DD);
#pragma unroll
        for (int r = 0; r < 4; r++) {
            wmma::fragment<wmma::matrix_a, 16, 16, 16, __half, wmma::row_major> af;
            wmma::load_matrix_sync(af, sA + (r * 16) * DD + k0 * 16, DD);
            wmma::mma_sync(c[r], af, bf, c[r]);
        }
    }

    // epilogue: reuse sA as per-warp fp32 staging (warp*256 floats each)
    __syncthreads();
    float* stage = reinterpret_cast<float*>(sA) + warp * 256;
#pragma unroll
    for (int r = 0; r < 4; r++) {
        wmma::store_matrix_sync(stage, c[r], 16, wmma::mem_row_major);
        __syncwarp();
        const float* src = &stage[lane * 8];
        int grow = row0 + r * 16 + (lane >> 1);
        if (grow < NN) {
            __half2 h[4];
#pragma unroll
            for (int j = 0; j < 4; j++)
                h[j] = __floats2half2_rn(src[2 * j], src[2 * j + 1]);
            *reinterpret_cast<uint4*>(&g_Yh[grow * DD + n0 + (lane & 1) * 8]) =
                *reinterpret_cast<uint4*>(&h[0]);
        }
        __syncwarp();
    }
}

// ---- K2: standalone edge scatter, 1024 edges/block, 4 per thread ----
__global__ void __launch_bounds__(256)
scatter_kernel(const int* __restrict__ senders,
               const int* __restrict__ receivers) {
    int e0 = blockIdx.x * 1024 + threadIdx.x * 4;
    int4 snd = *reinterpret_cast<const int4*>(&senders[e0]);
    int4 rcv = *reinterpret_cast<const int4*>(&receivers[e0]);
    int p0 = atomicAdd(&g_counts[rcv.x], 1);
    int p1 = atomicAdd(&g_counts[rcv.y], 1);
    int p2 = atomicAdd(&g_counts[rcv.z], 1);
    int p3 = atomicAdd(&g_counts[rcv.w], 1);
    g_sorted[rcv.x * CAP + p0] = snd.x;
    g_sorted[rcv.y * CAP + p1] = snd.y;
    g_sorted[rcv.z * CAP + p2] = snd.z;
    g_sorted[rcv.w * CAP + p3] = snd.w;
}

// ---- helper: reinterpret uint as half2 ----
__device__ __forceinline__ __half2 h2(unsigned int u) {
    return *reinterpret_cast<__half2*>(&u);
}

// ---- K3: warp-per-node aggregation (R7 verbatim: 8-deep LDG.64 + fp16 tree) ----
__global__ void __launch_bounds__(256)
agg_kernel(const float* __restrict__ b, float* __restrict__ out) {
    int warp = (blockIdx.x * blockDim.x + threadIdx.x) >> 5;
    int lane = threadIdx.x & 31;
    if (warp >= NN) return;

    const int deg  = g_counts[warp];
    const int base = warp * CAP;

    const uint2* Y2 = reinterpret_cast<const uint2*>(g_Yh);
    float4 acc = make_float4(0.f, 0.f, 0.f, 0.f);

    int i = 0;
    for (; i + 7 < deg; i += 8) {
        int4 ia = *reinterpret_cast<const int4*>(&g_sorted[base + i]);
        int4 ib = *reinterpret_cast<const int4*>(&g_sorted[base + i + 4]);
        uint2 v0 = Y2[ia.x * 32 + lane];
        uint2 v1 = Y2[ia.y * 32 + lane];
        uint2 v2 = Y2[ia.z * 32 + lane];
        uint2 v3 = Y2[ia.w * 32 + lane];
        uint2 v4 = Y2[ib.x * 32 + lane];
        uint2 v5 = Y2[ib.y * 32 + lane];
        uint2 v6 = Y2[ib.z * 32 + lane];
        uint2 v7 = Y2[ib.w * 32 + lane];
        __half2 pa0 = __hadd2(h2(v0.x), h2(v1.x)), pa1 = __hadd2(h2(v2.x), h2(v3.x));
        __half2 pa2 = __hadd2(h2(v4.x), h2(v5.x)), pa3 = __hadd2(h2(v6.x), h2(v7.x));
        __half2 pb0 = __hadd2(h2(v0.y), h2(v1.y)), pb1 = __hadd2(h2(v2.y), h2(v3.y));
        __half2 pb2 = __hadd2(h2(v4.y), h2(v5.y)), pb3 = __hadd2(h2(v6.y), h2(v7.y));
        __half2 qa = __hadd2(__hadd2(pa0, pa1), __hadd2(pa2, pa3));
        __half2 qb = __hadd2(__hadd2(pb0, pb1), __hadd2(pb2, pb3));
        float2 fa = __half22float2(qa);
        float2 fb = __half22float2(qb);
        acc.x += fa.x; acc.y += fa.y; acc.z += fb.x; acc.w += fb.y;
    }
    for (; i + 3 < deg; i += 4) {
        int4 ia = *reinterpret_cast<const int4*>(&g_sorted[base + i]);
        uint2 v0 = Y2[ia.x * 32 + lane];
        uint2 v1 = Y2[ia.y * 32 + lane];
        uint2 v2 = Y2[ia.z * 32 + lane];
        uint2 v3 = Y2[ia.w * 32 + lane];
        __half2 qa = __hadd2(__hadd2(h2(v0.x), h2(v1.x)), __hadd2(h2(v2.x), h2(v3.x)));
        __half2 qb = __hadd2(__hadd2(h2(v0.y), h2(v1.y)), __hadd2(h2(v2.y), h2(v3.y)));
        float2 fa = __half22float2(qa);
        float2 fb = __half22float2(qb);
        acc.x += fa.x; acc.y += fa.y; acc.z += fb.x; acc.w += fb.y;
    }
    for (; i < deg; i++) {
        int s0 = g_sorted[base + i];
        uint2 v = Y2[s0 * 32 + lane];
        float2 fa = __half22float2(h2(v.x));
        float2 fb = __half22float2(h2(v.y));
        acc.x += fa.x; acc.y += fa.y; acc.z += fb.x; acc.w += fb.y;
    }

    if (lane == 0) g_counts[warp] = 0;   // reset cursor for next replay

    float sc = 1.0f / (float)max(deg, 1);
    float4 bv = reinterpret_cast<const float4*>(b)[lane];
    float4 o;
    o.x = acc.x * sc + bv.x;
    o.y = acc.y * sc + bv.y;
    o.z = acc.z * sc + bv.z;
    o.w = acc.w * sc + bv.w;
    reinterpret_cast<float4*>(out)[warp * 32 + lane] = o;
}

extern "C" void kernel_launch(void* const* d_in, const int* in_sizes, int n_in,
                              void* d_out, int out_size) {
    const float* nodes     = (const float*)d_in[0];
    const int*   senders   = (const int*)d_in[1];
    const int*   receivers = (const int*)d_in[2];
    const float* W         = (const float*)d_in[3];
    const float* b         = (const float*)d_in[4];
    float*       out       = (float*)d_out;

    gemm_kernel<<<GEMM_TILES, 256>>>(nodes, W);
    scatter_kernel<<<SCAT_BLOCKS, 256>>>(senders, receivers);
    agg_kernel<<<(NN * 32 + 255) / 256, 256>>>(b, out);
}